// round 14
// baseline (speedup 1.0000x reference)
#include <cuda_runtime.h>
#include <cuda_fp16.h>
#include <math.h>
#include <cstdint>

// Problem constants
#define NB    16
#define NPTS  4096
#define MPTS  1024
#define CH2   256
#define CH1   128
#define OUT1  256
#define OUT2  256
#define LDA_W1 384
#define NSPLIT 4
#define MSPL  (MPTS / NSPLIT)   // 256 candidates per split

// ---- scratch ----
__device__ int    g_idx[NB * NPTS * 3];
__device__ float  g_wgt[NB * NPTS * 3];
__device__ float  g_pd [NSPLIT * NB * NPTS * 3];   // partial top-3 dists
__device__ int    g_pi [NSPLIT * NB * NPTS * 3];   // partial top-3 idx
__device__ float  g_Tt [NB * MPTS * OUT1];         // T transposed [b][m][o], fp32
__device__ __half g_y1h[NB * OUT1 * NPTS];
__device__ __half g_W1h[OUT1 * LDA_W1];
__device__ __half g_W2h[OUT2 * OUT1];
__device__ __half g_p1h[NB * CH1 * NPTS];
__device__ __half g_p2h[NB * CH2 * MPTS];

// ===========================================================================
__device__ __forceinline__ uint32_t smem_u32(const void* p) {
    uint32_t a;
    asm("{ .reg .u64 t; cvta.to.shared.u64 t, %1; cvt.u32.u64 %0, t; }" : "=r"(a) : "l"(p));
    return a;
}
__device__ __forceinline__ void cp16(void* dst, const void* src) {
    asm volatile("cp.async.ca.shared.global [%0], [%1], 16;"
                 :: "r"(smem_u32(dst)), "l"(src));
}
__device__ __forceinline__ void ldsm_x4(uint32_t addr, uint32_t& r0, uint32_t& r1,
                                        uint32_t& r2, uint32_t& r3) {
    asm volatile("ldmatrix.sync.aligned.m8n8.x4.shared.b16 {%0,%1,%2,%3}, [%4];"
                 : "=r"(r0), "=r"(r1), "=r"(r2), "=r"(r3) : "r"(addr));
}
__device__ __forceinline__ void ldsm_x4t(uint32_t addr, uint32_t& r0, uint32_t& r1,
                                         uint32_t& r2, uint32_t& r3) {
    asm volatile("ldmatrix.sync.aligned.m8n8.x4.trans.shared.b16 {%0,%1,%2,%3}, [%4];"
                 : "=r"(r0), "=r"(r1), "=r"(r2), "=r"(r3) : "r"(addr));
}
#define MMA_F16(C, A, B) \
    asm volatile( \
        "mma.sync.aligned.m16n8k16.row.col.f32.f16.f16.f32 " \
        "{%0,%1,%2,%3}, {%4,%5,%6,%7}, {%8,%9}, {%0,%1,%2,%3};" \
        : "+f"((C)[0]), "+f"((C)[1]), "+f"((C)[2]), "+f"((C)[3]) \
        : "r"((A)[0]), "r"((A)[1]), "r"((A)[2]), "r"((A)[3]), \
          "r"((B)[0]), "r"((B)[1]))

// ===========================================================================
// Kernel P1: blocks [0,1024) = 3nn partial (4-way M split);
//            blocks [1024,1280) = fp32->fp16 conversions.
// ===========================================================================
__global__ __launch_bounds__(256)
void prep_kernel(const float* __restrict__ xyz1, const float* __restrict__ xyz2,
                 const float* __restrict__ W1,  const float* __restrict__ W2,
                 const float* __restrict__ p1,  const float* __restrict__ p2)
{
    __shared__ float4 s_p2[MSPL];   // (x, y, z, |p|^2)

    const int blk = blockIdx.x;
    const int tid = threadIdx.x;

    if (blk >= 1024) {
        // ---- conversion quarter ----
        const int idx0   = (blk - 1024) * 256 + tid;
        const int stride = 256 * 256;
        auto conv = [&](const float* __restrict__ src, __half* __restrict__ dst, int n4) {
            for (int i = idx0; i < n4; i += stride) {
                float4 v = reinterpret_cast<const float4*>(src)[i];
                reinterpret_cast<__half2*>(dst)[2 * i + 0] = __floats2half2_rn(v.x, v.y);
                reinterpret_cast<__half2*>(dst)[2 * i + 1] = __floats2half2_rn(v.z, v.w);
            }
        };
        conv(W1, g_W1h, OUT1 * LDA_W1 / 4);
        conv(W2, g_W2h, OUT2 * OUT1 / 4);
        conv(p1, g_p1h, NB * CH1 * NPTS / 4);
        conv(p2, g_p2h, NB * CH2 * MPTS / 4);
        return;
    }

    // ---- three_nn partial: blk = ((b*16)+nblk)*4 + sp ----
    const int sp   = blk & 3;
    const int nblk = (blk >> 2) & 15;
    const int b    = blk >> 6;
    const int m0   = sp * MSPL;

    const float* x2 = xyz2 + (size_t)b * 3 * MPTS;
    for (int i = tid; i < MSPL; i += 256) {
        int m = m0 + i;
        float xv = x2[m], yv = x2[MPTS + m], zv = x2[2 * MPTS + m];
        s_p2[i] = make_float4(xv, yv, zv, xv * xv + yv * yv + zv * zv);
    }
    __syncthreads();

    const int n = nblk * 256 + tid;
    const float* x1 = xyz1 + (size_t)b * 3 * NPTS;
    const float px = x1[n], py = x1[NPTS + n], pz = x1[2 * NPTS + n];
    const float sq1 = px * px + py * py + pz * pz;

    float d0 = 1e30f, d1 = 1e30f, d2 = 1e30f;
    int   i0 = 0, i1 = 0, i2 = 0;

    #pragma unroll 8
    for (int j = 0; j < MSPL; j++) {
        float4 p = s_p2[j];
        float inner = fmaf(px, p.x, fmaf(py, p.y, pz * p.z));
        float d = fmaf(-2.0f, inner, sq1 + p.w);
        if (d < d2) {
            int m = m0 + j;
            if (d < d1) {
                d2 = d1; i2 = i1;
                if (d < d0) { d1 = d0; i1 = i0; d0 = d; i0 = m; }
                else        { d1 = d;  i1 = m; }
            } else { d2 = d; i2 = m; }
        }
    }

    const size_t base = (((size_t)sp * NB + b) * NPTS + n) * 3;
    g_pd[base + 0] = d0; g_pd[base + 1] = d1; g_pd[base + 2] = d2;
    g_pi[base + 0] = i0; g_pi[base + 1] = i1; g_pi[base + 2] = i2;
}

// ===========================================================================
// Kernel P2: merge 4 partial top-3 lists -> final idx/weights.
// Strict-< insertion in ascending split order == full sequential scan.
// ===========================================================================
__global__ __launch_bounds__(256)
void merge_kernel(void)
{
    const int q = blockIdx.x * 256 + threadIdx.x;   // 0 .. NB*NPTS-1

    float d0 = 1e30f, d1 = 1e30f, d2 = 1e30f;
    int   i0 = 0, i1 = 0, i2 = 0;

    #pragma unroll
    for (int sp = 0; sp < NSPLIT; sp++) {
        const size_t base = ((size_t)sp * NB * NPTS + q) * 3;
        #pragma unroll
        for (int k = 0; k < 3; k++) {
            float d = g_pd[base + k];
            int   m = g_pi[base + k];
            if (d < d2) {
                if (d < d1) {
                    d2 = d1; i2 = i1;
                    if (d < d0) { d1 = d0; i1 = i0; d0 = d; i0 = m; }
                    else        { d1 = d;  i1 = m; }
                } else { d2 = d; i2 = m; }
            }
        }
    }

    float r0 = 1.0f / fmaxf(sqrtf(fmaxf(d0, 1e-20f)), 1e-10f);
    float r1 = 1.0f / fmaxf(sqrtf(fmaxf(d1, 1e-20f)), 1e-10f);
    float r2 = 1.0f / fmaxf(sqrtf(fmaxf(d2, 1e-20f)), 1e-10f);
    float inv = 1.0f / (r0 + r1 + r2);

    g_idx[q * 3 + 0] = i0; g_idx[q * 3 + 1] = i1; g_idx[q * 3 + 2] = i2;
    g_wgt[q * 3 + 0] = r0 * inv; g_wgt[q * 3 + 1] = r1 * inv; g_wgt[q * 3 + 2] = r2 * inv;
}

// ===========================================================================
// fp16 mma.sync (m16n8k16) GEMM with ldmatrix + cp.async double buffer.
// 256-thr CTA, 8 warps (2x4), CTA tile 128x128, warp tile 64x32, BK=32.
//   MODE 0: Tt  = (W1h[:, :256] @ p2h)^T                  -> g_Tt [m][o] f32
//   MODE 1: y1h = h(relu(W1h[:,256:]@p1h + b1 + gather))  -> g_y1h
//   MODE 2: out = relu(W2h @ y1h + b2)                    -> d_out f32
// MODE 1: scattered gather interleaved into the chunk loop.
// ===========================================================================
#define BK    32
#define ASTR  40     // halves per As row (32 + 8 pad)
#define BSTR  136    // halves per Bs row (128 + 8 pad)

template <int MODE>
__global__ __launch_bounds__(256, 2)
void gemm_mma(const float* __restrict__ bias, float* __restrict__ Cext)
{
    constexpr int K    = (MODE == 1) ? 128 : 256;
    constexpr int NC   = K / BK;
    constexpr int LDA  = (MODE == 2) ? 256 : LDA_W1;
    constexpr int COFF = (MODE == 1) ? 256 : 0;
    constexpr int LDX  = (MODE == 0) ? MPTS : NPTS;
    constexpr int XBS  = (MODE == 0) ? CH2 * MPTS : (MODE == 1) ? CH1 * NPTS : OUT1 * NPTS;

    const __half* Ah = (MODE == 2) ? g_W2h : g_W1h;
    const __half* Xh = (MODE == 0) ? g_p2h : (MODE == 1) ? g_p1h : g_y1h;

    __shared__ __align__(16) __half As[2][128][ASTR];   // 20.0 KB
    __shared__ __align__(16) __half Bs[2][BK][BSTR];    // 17.4 KB
    __shared__ int   s_j[128 * 3];
    __shared__ float s_w[128 * 3];

    const int b     = blockIdx.z;
    const int nBase = blockIdx.x * 128;
    const int oBase = blockIdx.y * 128;
    const int tid   = threadIdx.x;
    const int wid   = tid >> 5;
    const int lane  = tid & 31;
    const int g     = lane >> 2;
    const int tc    = lane & 3;

    const int oW = (wid >> 2) * 64;
    const int nW = (wid & 3) * 32;

    const __half* Xb = Xh + (size_t)b * XBS;

    if (MODE == 1) {
        const int*   gi = g_idx + ((size_t)b * NPTS + nBase) * 3;
        const float* gw = g_wgt + ((size_t)b * NPTS + nBase) * 3;
        for (int i = tid; i < 384; i += 256) { s_j[i] = gi[i]; s_w[i] = gw[i]; }
    }

    const int arow = tid & 127;
    const int akc0 = tid >> 7;
    const int bk0  = tid >> 4;
    const int bn8  = tid & 15;

    auto prefetch = [&](int c) {
        const int buf = c & 1;
        const int k0  = c * BK;
        const __half* ap = &Ah[(size_t)(oBase + arow) * LDA + COFF + k0];
        cp16(&As[buf][arow][8 * akc0],       ap + 8 * akc0);
        cp16(&As[buf][arow][8 * (akc0 + 2)], ap + 8 * (akc0 + 2));
        const __half* bp = &Xb[(size_t)k0 * LDX + nBase + 8 * bn8];
        cp16(&Bs[buf][bk0     ][8 * bn8], bp + (size_t)bk0 * LDX);
        cp16(&Bs[buf][bk0 + 16][8 * bn8], bp + (size_t)(bk0 + 16) * LDX);
        asm volatile("cp.async.commit_group;" ::: "memory");
    };

    const int lm = lane >> 3;
    const int lr = lane & 7;
    uint32_t aoff[4];
    #pragma unroll
    for (int mi = 0; mi < 4; mi++)
        aoff[mi] = ((oW + mi * 16 + lr + 8 * (lm & 1)) * ASTR + 8 * (lm >> 1)) * 2;
    uint32_t boff[2];
    #pragma unroll
    for (int pr = 0; pr < 2; pr++)
        boff[pr] = ((lr + 8 * (lm & 1)) * BSTR + nW + pr * 16 + 8 * (lm >> 1)) * 2;

    const uint32_t as_base = smem_u32(&As[0][0][0]);
    const uint32_t bs_base = smem_u32(&Bs[0][0][0]);
    constexpr uint32_t AS_BUF = 128 * ASTR * 2;
    constexpr uint32_t BS_BUF = BK * BSTR * 2;

    const float* Tb = g_Tt + (size_t)b * MPTS * OUT1;

    float c[4][4][4];
    #pragma unroll
    for (int mi = 0; mi < 4; mi++)
        #pragma unroll
        for (int ni = 0; ni < 4; ni++)
            #pragma unroll
            for (int q = 0; q < 4; q++) c[mi][ni][q] = 0.0f;

    prefetch(0);
    asm volatile("cp.async.wait_group 0;" ::: "memory");
    __syncthreads();

    for (int cc = 0; cc < NC; cc++) {
        const uint32_t asb = as_base + (cc & 1) * AS_BUF;
        const uint32_t bsb = bs_base + (cc & 1) * BS_BUF;
        if (cc + 1 < NC) prefetch(cc + 1);

        #pragma unroll
        for (int kk = 0; kk < BK; kk += 16) {
            uint32_t a[4][4];
            #pragma unroll
            for (int mi = 0; mi < 4; mi++)
                ldsm_x4(asb + aoff[mi] + kk * 2, a[mi][0], a[mi][1], a[mi][2], a[mi][3]);
            uint32_t bb[4][2];
            ldsm_x4t(bsb + boff[0] + kk * (BSTR * 2), bb[0][0], bb[0][1], bb[1][0], bb[1][1]);
            ldsm_x4t(bsb + boff[1] + kk * (BSTR * 2), bb[2][0], bb[2][1], bb[3][0], bb[3][1]);
            #pragma unroll
            for (int mi = 0; mi < 4; mi++)
                #pragma unroll
                for (int ni = 0; ni < 4; ni++)
                    MMA_F16(c[mi][ni], a[mi], bb[ni]);
        }

        if (MODE == 1) {
            const int gni = (cc + 3) & 3;
            #pragma unroll
            for (int t = 0; t < 2; t++) {
                const int ncta = nW + gni * 8 + tc * 2 + t;
                const int j0 = s_j[ncta * 3 + 0];
                const int j1 = s_j[ncta * 3 + 1];
                const int j2 = s_j[ncta * 3 + 2];
                const float w0 = s_w[ncta * 3 + 0];
                const float w1 = s_w[ncta * 3 + 1];
                const float w2 = s_w[ncta * 3 + 2];
                const float* r0 = Tb + (size_t)j0 * OUT1 + oBase + oW;
                const float* r1 = Tb + (size_t)j1 * OUT1 + oBase + oW;
                const float* r2 = Tb + (size_t)j2 * OUT1 + oBase + oW;
                #pragma unroll
                for (int mi = 0; mi < 4; mi++) {
                    #pragma unroll
                    for (int h = 0; h < 2; h++) {
                        const int ol = mi * 16 + g + h * 8;
                        c[mi][gni][h * 2 + t] +=
                            w0 * __ldg(&r0[ol]) + w1 * __ldg(&r1[ol]) + w2 * __ldg(&r2[ol]);
                    }
                }
            }
        }

        asm volatile("cp.async.wait_group 0;" ::: "memory");
        __syncthreads();
    }

    // ---- epilogue ----
    if (MODE == 0) {
        float* Cb = g_Tt + (size_t)b * MPTS * OUT1;
        #pragma unroll
        for (int ni = 0; ni < 4; ni++) {
            #pragma unroll
            for (int t = 0; t < 2; t++) {
                int m = nBase + nW + ni * 8 + tc * 2 + t;
                float* mrow = Cb + (size_t)m * OUT1;
                #pragma unroll
                for (int mi = 0; mi < 4; mi++) {
                    #pragma unroll
                    for (int h = 0; h < 2; h++) {
                        int o = oBase + oW + mi * 16 + g + h * 8;
                        mrow[o] = c[mi][ni][h * 2 + t];
                    }
                }
            }
        }
        return;
    }

    if (MODE == 1) {
        __half* Cb = g_y1h + (size_t)b * OUT1 * NPTS;
        #pragma unroll
        for (int mi = 0; mi < 4; mi++) {
            #pragma unroll
            for (int h = 0; h < 2; h++) {
                int o = oBase + oW + mi * 16 + g + h * 8;
                float bv = bias[o];
                __half* orow = Cb + (size_t)o * NPTS;
                #pragma unroll
                for (int ni = 0; ni < 4; ni++) {
                    int n = nBase + nW + ni * 8 + tc * 2;
                    float v0 = fmaxf(c[mi][ni][h * 2 + 0] + bv, 0.0f);
                    float v1 = fmaxf(c[mi][ni][h * 2 + 1] + bv, 0.0f);
                    *reinterpret_cast<__half2*>(&orow[n]) = __floats2half2_rn(v0, v1);
                }
            }
        }
        return;
    }

    // MODE 2: final output fp32
    float* Cb = Cext + (size_t)b * OUT2 * NPTS;
    #pragma unroll
    for (int mi = 0; mi < 4; mi++) {
        #pragma unroll
        for (int h = 0; h < 2; h++) {
            int o = oBase + oW + mi * 16 + g + h * 8;
            float bv = bias[o];
            float* orow = Cb + (size_t)o * NPTS;
            #pragma unroll
            for (int ni = 0; ni < 4; ni++) {
                int n = nBase + nW + ni * 8 + tc * 2;
                float v0 = fmaxf(c[mi][ni][h * 2 + 0] + bv, 0.0f);
                float v1 = fmaxf(c[mi][ni][h * 2 + 1] + bv, 0.0f);
                *reinterpret_cast<float2*>(&orow[n]) = make_float2(v0, v1);
            }
        }
    }
}

// ===========================================================================
extern "C" void kernel_launch(void* const* d_in, const int* in_sizes, int n_in,
                              void* d_out, int out_size)
{
    const float* xyz1    = (const float*)d_in[0];
    const float* xyz2    = (const float*)d_in[1];
    const float* points1 = (const float*)d_in[2];
    const float* points2 = (const float*)d_in[3];
    const float* W1      = (const float*)d_in[4];
    const float* b1      = (const float*)d_in[5];
    const float* W2      = (const float*)d_in[6];
    const float* b2      = (const float*)d_in[7];
    float*       out     = (float*)d_out;

    // 3nn partials (4-way M split) + fp16 conversion, one grid
    prep_kernel<<<1280, 256>>>(xyz1, xyz2, W1, W2, points1, points2);

    // merge partial top-3 -> idx/weights
    merge_kernel<<<NB * NPTS / 256, 256>>>();

    // Tt = (W1[:, :256] @ points2)^T  (fp32)
    gemm_mma<0><<<dim3(MPTS / 128, OUT1 / 128, NB), 256>>>(nullptr, nullptr);

    // y1h = half(relu(W1[:, 256:] @ points1 + b1 + gathered Tt))
    gemm_mma<1><<<dim3(NPTS / 128, OUT1 / 128, NB), 256>>>(b1, nullptr);

    // out = relu(W2 @ y1h + b2)
    gemm_mma<2><<<dim3(NPTS / 128, OUT2 / 128, NB), 256>>>(b2, out);
}

// round 15
// speedup vs baseline: 1.5240x; 1.5240x over previous
#include <cuda_runtime.h>
#include <cuda_fp16.h>
#include <math.h>
#include <cstdint>

// Problem constants
#define NB    16
#define NPTS  4096
#define MPTS  1024
#define CH2   256
#define CH1   128
#define OUT1  256
#define OUT2  256
#define LDA_W1 384

// ---- scratch ----
__device__ int    g_idx[NB * NPTS * 3];
__device__ float  g_wgt[NB * NPTS * 3];
__device__ float  g_Tt [NB * MPTS * OUT1];    // T transposed [b][m][o], fp32 (gather src)
__device__ __half g_y1h[NB * OUT1 * NPTS];    // layer-1 activations, half
__device__ __half g_W1h[OUT1 * LDA_W1];
__device__ __half g_W2h[OUT2 * OUT1];
__device__ __half g_p1h[NB * CH1 * NPTS];
__device__ __half g_p2h[NB * CH2 * MPTS];

// ===========================================================================
__device__ __forceinline__ uint32_t smem_u32(const void* p) {
    uint32_t a;
    asm("{ .reg .u64 t; cvta.to.shared.u64 t, %1; cvt.u32.u64 %0, t; }" : "=r"(a) : "l"(p));
    return a;
}
__device__ __forceinline__ void cp16(void* dst, const void* src) {
    asm volatile("cp.async.ca.shared.global [%0], [%1], 16;"
                 :: "r"(smem_u32(dst)), "l"(src));
}
__device__ __forceinline__ void ldsm_x4(uint32_t addr, uint32_t& r0, uint32_t& r1,
                                        uint32_t& r2, uint32_t& r3) {
    asm volatile("ldmatrix.sync.aligned.m8n8.x4.shared.b16 {%0,%1,%2,%3}, [%4];"
                 : "=r"(r0), "=r"(r1), "=r"(r2), "=r"(r3) : "r"(addr));
}
__device__ __forceinline__ void ldsm_x4t(uint32_t addr, uint32_t& r0, uint32_t& r1,
                                         uint32_t& r2, uint32_t& r3) {
    asm volatile("ldmatrix.sync.aligned.m8n8.x4.trans.shared.b16 {%0,%1,%2,%3}, [%4];"
                 : "=r"(r0), "=r"(r1), "=r"(r2), "=r"(r3) : "r"(addr));
}
#define MMA_F16(C, A, B) \
    asm volatile( \
        "mma.sync.aligned.m16n8k16.row.col.f32.f16.f16.f32 " \
        "{%0,%1,%2,%3}, {%4,%5,%6,%7}, {%8,%9}, {%0,%1,%2,%3};" \
        : "+f"((C)[0]), "+f"((C)[1]), "+f"((C)[2]), "+f"((C)[3]) \
        : "r"((A)[0]), "r"((A)[1]), "r"((A)[2]), "r"((A)[3]), \
          "r"((B)[0]), "r"((B)[1]))

// ===========================================================================
// Kernel A (merged, 128-thr CTAs): blocks [0,512) = three_nn (128 queries
// each, FULL 1024-candidate scan — selection identical to R12);
// blocks [512,768) = fp32->fp16 conversions.
// ===========================================================================
__global__ __launch_bounds__(128)
void prep_kernel(const float* __restrict__ xyz1, const float* __restrict__ xyz2,
                 const float* __restrict__ W1,  const float* __restrict__ W2,
                 const float* __restrict__ p1,  const float* __restrict__ p2)
{
    __shared__ float4 s_p2[MPTS];   // (x, y, z, |p|^2)  16KB

    const int blk = blockIdx.x;
    const int tid = threadIdx.x;

    if (blk >= 512) {
        // ---- conversion half ----
        const int idx0   = (blk - 512) * 128 + tid;
        const int stride = 256 * 128;
        auto conv = [&](const float* __restrict__ src, __half* __restrict__ dst, int n4) {
            for (int i = idx0; i < n4; i += stride) {
                float4 v = reinterpret_cast<const float4*>(src)[i];
                reinterpret_cast<__half2*>(dst)[2 * i + 0] = __floats2half2_rn(v.x, v.y);
                reinterpret_cast<__half2*>(dst)[2 * i + 1] = __floats2half2_rn(v.z, v.w);
            }
        };
        conv(W1, g_W1h, OUT1 * LDA_W1 / 4);
        conv(W2, g_W2h, OUT2 * OUT1 / 4);
        conv(p1, g_p1h, NB * CH1 * NPTS / 4);
        conv(p2, g_p2h, NB * CH2 * MPTS / 4);
        return;
    }

    // ---- three_nn half: blk = b*32 + nblk ----
    const int b    = blk >> 5;          // 0..15
    const int nblk = blk & 31;          // 0..31
    const float* x2 = xyz2 + (size_t)b * 3 * MPTS;
    for (int i = tid; i < MPTS; i += 128) {
        float xv = x2[i], yv = x2[MPTS + i], zv = x2[2 * MPTS + i];
        s_p2[i] = make_float4(xv, yv, zv, xv * xv + yv * yv + zv * zv);
    }
    __syncthreads();

    const int n = nblk * 128 + tid;
    const float* x1 = xyz1 + (size_t)b * 3 * NPTS;
    const float px = x1[n], py = x1[NPTS + n], pz = x1[2 * NPTS + n];
    const float sq1 = px * px + py * py + pz * pz;

    float d0 = 1e30f, d1 = 1e30f, d2 = 1e30f;
    int   i0 = 0, i1 = 0, i2 = 0;

    #pragma unroll 8
    for (int m = 0; m < MPTS; m++) {
        float4 p = s_p2[m];
        float inner = fmaf(px, p.x, fmaf(py, p.y, pz * p.z));
        float d = fmaf(-2.0f, inner, sq1 + p.w);
        if (d < d2) {
            if (d < d1) {
                d2 = d1; i2 = i1;
                if (d < d0) { d1 = d0; i1 = i0; d0 = d; i0 = m; }
                else        { d1 = d;  i1 = m; }
            } else { d2 = d; i2 = m; }
        }
    }

    float r0 = 1.0f / fmaxf(sqrtf(fmaxf(d0, 1e-20f)), 1e-10f);
    float r1 = 1.0f / fmaxf(sqrtf(fmaxf(d1, 1e-20f)), 1e-10f);
    float r2 = 1.0f / fmaxf(sqrtf(fmaxf(d2, 1e-20f)), 1e-10f);
    float inv = 1.0f / (r0 + r1 + r2);

    const int base = (b * NPTS + n) * 3;
    g_idx[base + 0] = i0; g_idx[base + 1] = i1; g_idx[base + 2] = i2;
    g_wgt[base + 0] = r0 * inv; g_wgt[base + 1] = r1 * inv; g_wgt[base + 2] = r2 * inv;
}

// ===========================================================================
// fp16 mma.sync (m16n8k16) GEMM with ldmatrix + cp.async double buffer.
// 256-thr CTA, 8 warps (2x4), CTA tile 128x128, warp tile 64x32, BK=32.
//   MODE 0: Tt  = (W1h[:, :256] @ p2h)^T                  -> g_Tt [m][o] f32
//   MODE 1: y1h = h(relu(W1h[:,256:]@p1h + b1 + gather))  -> g_y1h
//   MODE 2: out = relu(W2h @ y1h + b2)                    -> d_out f32
// MODE 1: scattered gather interleaved into the chunk loop (ni group
// (cc+3)&3 gathered in chunk cc).
// ===========================================================================
#define BK    32
#define ASTR  40     // halves per As row (32 + 8 pad)
#define BSTR  136    // halves per Bs row (128 + 8 pad)

template <int MODE>
__global__ __launch_bounds__(256, 2)
void gemm_mma(const float* __restrict__ bias, float* __restrict__ Cext)
{
    constexpr int K    = (MODE == 1) ? 128 : 256;
    constexpr int NC   = K / BK;
    constexpr int LDA  = (MODE == 2) ? 256 : LDA_W1;
    constexpr int COFF = (MODE == 1) ? 256 : 0;
    constexpr int LDX  = (MODE == 0) ? MPTS : NPTS;
    constexpr int XBS  = (MODE == 0) ? CH2 * MPTS : (MODE == 1) ? CH1 * NPTS : OUT1 * NPTS;

    const __half* Ah = (MODE == 2) ? g_W2h : g_W1h;
    const __half* Xh = (MODE == 0) ? g_p2h : (MODE == 1) ? g_p1h : g_y1h;

    __shared__ __align__(16) __half As[2][128][ASTR];   // 20.0 KB
    __shared__ __align__(16) __half Bs[2][BK][BSTR];    // 17.4 KB
    __shared__ int   s_j[128 * 3];
    __shared__ float s_w[128 * 3];

    const int b     = blockIdx.z;
    const int nBase = blockIdx.x * 128;
    const int oBase = blockIdx.y * 128;
    const int tid   = threadIdx.x;
    const int wid   = tid >> 5;
    const int lane  = tid & 31;
    const int g     = lane >> 2;
    const int tc    = lane & 3;

    const int oW = (wid >> 2) * 64;
    const int nW = (wid & 3) * 32;

    const __half* Xb = Xh + (size_t)b * XBS;

    if (MODE == 1) {
        const int*   gi = g_idx + ((size_t)b * NPTS + nBase) * 3;
        const float* gw = g_wgt + ((size_t)b * NPTS + nBase) * 3;
        for (int i = tid; i < 384; i += 256) { s_j[i] = gi[i]; s_w[i] = gw[i]; }
    }

    const int arow = tid & 127;
    const int akc0 = tid >> 7;
    const int bk0  = tid >> 4;
    const int bn8  = tid & 15;

    auto prefetch = [&](int c) {
        const int buf = c & 1;
        const int k0  = c * BK;
        const __half* ap = &Ah[(size_t)(oBase + arow) * LDA + COFF + k0];
        cp16(&As[buf][arow][8 * akc0],       ap + 8 * akc0);
        cp16(&As[buf][arow][8 * (akc0 + 2)], ap + 8 * (akc0 + 2));
        const __half* bp = &Xb[(size_t)k0 * LDX + nBase + 8 * bn8];
        cp16(&Bs[buf][bk0     ][8 * bn8], bp + (size_t)bk0 * LDX);
        cp16(&Bs[buf][bk0 + 16][8 * bn8], bp + (size_t)(bk0 + 16) * LDX);
        asm volatile("cp.async.commit_group;" ::: "memory");
    };

    const int lm = lane >> 3;
    const int lr = lane & 7;
    uint32_t aoff[4];
    #pragma unroll
    for (int mi = 0; mi < 4; mi++)
        aoff[mi] = ((oW + mi * 16 + lr + 8 * (lm & 1)) * ASTR + 8 * (lm >> 1)) * 2;
    uint32_t boff[2];
    #pragma unroll
    for (int pr = 0; pr < 2; pr++)
        boff[pr] = ((lr + 8 * (lm & 1)) * BSTR + nW + pr * 16 + 8 * (lm >> 1)) * 2;

    const uint32_t as_base = smem_u32(&As[0][0][0]);
    const uint32_t bs_base = smem_u32(&Bs[0][0][0]);
    constexpr uint32_t AS_BUF = 128 * ASTR * 2;
    constexpr uint32_t BS_BUF = BK * BSTR * 2;

    const float* Tb = g_Tt + (size_t)b * MPTS * OUT1;

    float c[4][4][4];
    #pragma unroll
    for (int mi = 0; mi < 4; mi++)
        #pragma unroll
        for (int ni = 0; ni < 4; ni++)
            #pragma unroll
            for (int q = 0; q < 4; q++) c[mi][ni][q] = 0.0f;

    prefetch(0);
    asm volatile("cp.async.wait_group 0;" ::: "memory");
    __syncthreads();

    for (int cc = 0; cc < NC; cc++) {
        const uint32_t asb = as_base + (cc & 1) * AS_BUF;
        const uint32_t bsb = bs_base + (cc & 1) * BS_BUF;
        if (cc + 1 < NC) prefetch(cc + 1);

        #pragma unroll
        for (int kk = 0; kk < BK; kk += 16) {
            uint32_t a[4][4];
            #pragma unroll
            for (int mi = 0; mi < 4; mi++)
                ldsm_x4(asb + aoff[mi] + kk * 2, a[mi][0], a[mi][1], a[mi][2], a[mi][3]);
            uint32_t bb[4][2];
            ldsm_x4t(bsb + boff[0] + kk * (BSTR * 2), bb[0][0], bb[0][1], bb[1][0], bb[1][1]);
            ldsm_x4t(bsb + boff[1] + kk * (BSTR * 2), bb[2][0], bb[2][1], bb[3][0], bb[3][1]);
            #pragma unroll
            for (int mi = 0; mi < 4; mi++)
                #pragma unroll
                for (int ni = 0; ni < 4; ni++)
                    MMA_F16(c[mi][ni], a[mi], bb[ni]);
        }

        if (MODE == 1) {
            const int gni = (cc + 3) & 3;
            #pragma unroll
            for (int t = 0; t < 2; t++) {
                const int ncta = nW + gni * 8 + tc * 2 + t;
                const int j0 = s_j[ncta * 3 + 0];
                const int j1 = s_j[ncta * 3 + 1];
                const int j2 = s_j[ncta * 3 + 2];
                const float w0 = s_w[ncta * 3 + 0];
                const float w1 = s_w[ncta * 3 + 1];
                const float w2 = s_w[ncta * 3 + 2];
                const float* r0 = Tb + (size_t)j0 * OUT1 + oBase + oW;
                const float* r1 = Tb + (size_t)j1 * OUT1 + oBase + oW;
                const float* r2 = Tb + (size_t)j2 * OUT1 + oBase + oW;
                #pragma unroll
                for (int mi = 0; mi < 4; mi++) {
                    #pragma unroll
                    for (int h = 0; h < 2; h++) {
                        const int ol = mi * 16 + g + h * 8;
                        c[mi][gni][h * 2 + t] +=
                            w0 * __ldg(&r0[ol]) + w1 * __ldg(&r1[ol]) + w2 * __ldg(&r2[ol]);
                    }
                }
            }
        }

        asm volatile("cp.async.wait_group 0;" ::: "memory");
        __syncthreads();
    }

    // ---- epilogue ----
    if (MODE == 0) {
        float* Cb = g_Tt + (size_t)b * MPTS * OUT1;
        #pragma unroll
        for (int ni = 0; ni < 4; ni++) {
            #pragma unroll
            for (int t = 0; t < 2; t++) {
                int m = nBase + nW + ni * 8 + tc * 2 + t;
                float* mrow = Cb + (size_t)m * OUT1;
                #pragma unroll
                for (int mi = 0; mi < 4; mi++) {
                    #pragma unroll
                    for (int h = 0; h < 2; h++) {
                        int o = oBase + oW + mi * 16 + g + h * 8;
                        mrow[o] = c[mi][ni][h * 2 + t];
                    }
                }
            }
        }
        return;
    }

    if (MODE == 1) {
        __half* Cb = g_y1h + (size_t)b * OUT1 * NPTS;
        #pragma unroll
        for (int mi = 0; mi < 4; mi++) {
            #pragma unroll
            for (int h = 0; h < 2; h++) {
                int o = oBase + oW + mi * 16 + g + h * 8;
                float bv = bias[o];
                __half* orow = Cb + (size_t)o * NPTS;
                #pragma unroll
                for (int ni = 0; ni < 4; ni++) {
                    int n = nBase + nW + ni * 8 + tc * 2;
                    float v0 = fmaxf(c[mi][ni][h * 2 + 0] + bv, 0.0f);
                    float v1 = fmaxf(c[mi][ni][h * 2 + 1] + bv, 0.0f);
                    *reinterpret_cast<__half2*>(&orow[n]) = __floats2half2_rn(v0, v1);
                }
            }
        }
        return;
    }

    // MODE 2: final output fp32
    float* Cb = Cext + (size_t)b * OUT2 * NPTS;
    #pragma unroll
    for (int mi = 0; mi < 4; mi++) {
        #pragma unroll
        for (int h = 0; h < 2; h++) {
            int o = oBase + oW + mi * 16 + g + h * 8;
            float bv = bias[o];
            float* orow = Cb + (size_t)o * NPTS;
            #pragma unroll
            for (int ni = 0; ni < 4; ni++) {
                int n = nBase + nW + ni * 8 + tc * 2;
                float v0 = fmaxf(c[mi][ni][h * 2 + 0] + bv, 0.0f);
                float v1 = fmaxf(c[mi][ni][h * 2 + 1] + bv, 0.0f);
                *reinterpret_cast<float2*>(&orow[n]) = make_float2(v0, v1);
            }
        }
    }
}

// ===========================================================================
extern "C" void kernel_launch(void* const* d_in, const int* in_sizes, int n_in,
                              void* d_out, int out_size)
{
    const float* xyz1    = (const float*)d_in[0];
    const float* xyz2    = (const float*)d_in[1];
    const float* points1 = (const float*)d_in[2];
    const float* points2 = (const float*)d_in[3];
    const float* W1      = (const float*)d_in[4];
    const float* b1      = (const float*)d_in[5];
    const float* W2      = (const float*)d_in[6];
    const float* b2      = (const float*)d_in[7];
    float*       out     = (float*)d_out;

    // three_nn (512 CTAs x 128 queries) + fp16 conversion (256 CTAs), one grid
    prep_kernel<<<768, 128>>>(xyz1, xyz2, W1, W2, points1, points2);

    // Tt = (W1[:, :256] @ points2)^T   (fp32)
    gemm_mma<0><<<dim3(MPTS / 128, OUT1 / 128, NB), 256>>>(nullptr, nullptr);

    // y1h = half(relu(W1[:, 256:] @ points1 + b1 + gathered Tt))
    gemm_mma<1><<<dim3(NPTS / 128, OUT1 / 128, NB), 256>>>(b1, nullptr);

    // out = relu(W2 @ y1h + b2)
    gemm_mma<2><<<dim3(NPTS / 128, OUT2 / 128, NB), 256>>>(b2, out);
}